// round 2
// baseline (speedup 1.0000x reference)
#include <cuda_runtime.h>
#include <cstdint>

#define SS 8
#define NN 512
#define CC 128
#define HH 128

// Scratch: channels-last fmap pyramid per plane + scaled init track features.
__device__ float g_P0[(size_t)3 * SS * HH * HH * CC];     // [3*S][128][128][C]
__device__ float g_P1[(size_t)3 * SS * 64 * 64 * CC];
__device__ float g_P2[(size_t)3 * SS * 32 * 32 * CC];
__device__ float g_P3[(size_t)3 * SS * 16 * 16 * CC];
__device__ float g_T [(size_t)3 * NN * CC];               // t / sqrt(C)

// ---------------------------------------------------------------------------
// Transpose [S,C,H,W] -> [S,H,W,C] per plane (channels-last for coalesced dots)
// ---------------------------------------------------------------------------
__global__ void transpose_kernel(const float* __restrict__ fxy,
                                 const float* __restrict__ fyz,
                                 const float* __restrict__ fxz) {
    int ps = blockIdx.z;              // p*S + s
    int p = ps / SS, s = ps % SS;
    const float* src = (p == 0 ? fxy : (p == 1 ? fyz : fxz)) + (size_t)s * CC * HH * HH;
    float* dst = g_P0 + (size_t)ps * HH * HH * CC;

    __shared__ float tile[32][33];
    int m0 = blockIdx.x * 32;         // pixel (h*W+w) tile
    int c0 = blockIdx.y * 32;         // channel tile
    int tx = threadIdx.x, ty = threadIdx.y;   // (32, 8)

#pragma unroll
    for (int k = 0; k < 4; k++) {
        int c = c0 + ty + k * 8;
        tile[ty + k * 8][tx] = src[(size_t)c * (HH * HH) + m0 + tx];
    }
    __syncthreads();
#pragma unroll
    for (int k = 0; k < 4; k++) {
        int m = m0 + ty + k * 8;
        dst[(size_t)m * CC + c0 + tx] = tile[tx][ty + k * 8];
    }
}

// ---------------------------------------------------------------------------
// 2x2 average pool, channels-last, float4 per thread
// ---------------------------------------------------------------------------
__global__ void pool_kernel(int level) {
    const float* src; float* dst; int Ws;
    if (level == 0)      { src = g_P0; dst = g_P1; Ws = 128; }
    else if (level == 1) { src = g_P1; dst = g_P2; Ws = 64; }
    else                 { src = g_P2; dst = g_P3; Ws = 32; }
    int Wd = Ws >> 1;

    size_t idx = (size_t)blockIdx.x * blockDim.x + threadIdx.x;
    size_t total = (size_t)3 * SS * Wd * Wd * (CC / 4);
    if (idx >= total) return;

    int c4 = (int)(idx & 31);
    size_t r = idx >> 5;
    int xx = (int)(r % Wd); r /= Wd;
    int yy = (int)(r % Wd); r /= Wd;   // r = ps

    const float* sp = src + (((r * Ws + 2 * yy) * Ws + 2 * xx) << 7) + (c4 << 2);
    float4 a = *(const float4*)sp;
    float4 b = *(const float4*)(sp + CC);
    float4 c = *(const float4*)(sp + ((size_t)Ws << 7));
    float4 d = *(const float4*)(sp + ((size_t)Ws << 7) + CC);
    float4 o;
    o.x = (a.x + b.x + c.x + d.x) * 0.25f;
    o.y = (a.y + b.y + c.y + d.y) * 0.25f;
    o.z = (a.z + b.z + c.z + d.z) * 0.25f;
    o.w = (a.w + b.w + c.w + d.w) * 0.25f;
    *(float4*)(dst + (((r * Wd + yy) * Wd + xx) << 7) + (c4 << 2)) = o;
}

// ---------------------------------------------------------------------------
// Init track features: bilinear sample at coords[s=0] in frame queried_t[n],
// pre-scaled by 1/sqrt(C).
// ---------------------------------------------------------------------------
__global__ void init_kernel(const float* __restrict__ coords,
                            const int* __restrict__ qt) {
    int n = blockIdx.x, p = blockIdx.y, c = threadIdx.x;
    float x = coords[n * 3 + 0], y = coords[n * 3 + 1], z = coords[n * 3 + 2];
    float u = (p == 0) ? x : (p == 1 ? y : x);
    float v = (p == 0) ? y : z;
    int f = qt[n];
    const float* base = g_P0 + (size_t)(p * SS + f) * HH * HH * CC;

    u = fminf(fmaxf(u, 0.f), (float)(HH - 1));
    v = fminf(fmaxf(v, 0.f), (float)(HH - 1));
    int x0 = min(max((int)floorf(u), 0), HH - 2);
    int y0 = min(max((int)floorf(v), 0), HH - 2);
    float wx = u - (float)x0, wy = v - (float)y0;

    const float* b00 = base + ((size_t)(y0 * HH + x0) << 7);
    float v00 = b00[c];
    float v01 = b00[CC + c];
    float v10 = b00[(HH << 7) + c];
    float v11 = b00[(HH << 7) + CC + c];
    float val = v00 * (1.f - wx) * (1.f - wy) + v01 * wx * (1.f - wy)
              + v10 * (1.f - wx) * wy + v11 * wx * wy;
    g_T[(size_t)(p * NN + n) * CC + c] = val * 0.08838834764831845f; // 1/sqrt(128)
}

// ---------------------------------------------------------------------------
// Main: per (plane, s, n): 8x8 grid of corr dots per level -> 49 taps,
// plus full-res bilinear feature sample.
// ---------------------------------------------------------------------------
__global__ void __launch_bounds__(128) main_kernel(const float* __restrict__ coords,
                                                   float* __restrict__ out) {
    int n = blockIdx.x, s = blockIdx.y, p = blockIdx.z;
    int tid = threadIdx.x, lane = tid & 31, w = tid >> 5;
    int ps = p * SS + s;

    const float* cc = coords + (size_t)(s * NN + n) * 3;
    float x = cc[0], y = cc[1], z = cc[2];
    float u = (p == 0) ? x : (p == 1 ? y : x);
    float v = (p == 0) ? y : z;

    __shared__ float sT[CC];
    __shared__ float G[64];
    sT[tid] = g_T[(size_t)(p * NN + n) * CC + tid];
    __syncthreads();
    float4 tt = ((const float4*)sT)[lane];

    float* ob = out + ((size_t)s * NN + n) * 972;

    const float* base0 = g_P0 + (size_t)ps * HH * HH * CC;
    const float* base1 = g_P1 + (size_t)ps * 64 * 64 * CC;
    const float* base2 = g_P2 + (size_t)ps * 32 * 32 * CC;
    const float* base3 = g_P3 + (size_t)ps * 16 * 16 * CC;

#pragma unroll
    for (int l = 0; l < 4; l++) {
        const int Wl = HH >> l;
        const float sc = 1.0f / (float)(1 << l);
        const float* base = (l == 0) ? base0 : (l == 1) ? base1 : (l == 2) ? base2 : base3;

        float cx = u * sc, cy = v * sc;
        int bx = (int)floorf(cx), by = (int)floorf(cy);

        // 64 grid dot products; warp handles 16 positions
#pragma unroll
        for (int q = 0; q < 16; q++) {
            int pos = w * 16 + q;
            int gi = pos >> 3, gj = pos & 7;
            int gy = min(max(by - 3 + gi, 0), Wl - 1);
            int gx = min(max(bx - 3 + gj, 0), Wl - 1);
            const float4 f = *(const float4*)(base + ((size_t)(gy * Wl + gx) << 7) + (lane << 2));
            float dv = f.x * tt.x + f.y * tt.y + f.z * tt.z + f.w * tt.w;
            dv += __shfl_xor_sync(0xffffffffu, dv, 16);
            dv += __shfl_xor_sync(0xffffffffu, dv, 8);
            dv += __shfl_xor_sync(0xffffffffu, dv, 4);
            dv += __shfl_xor_sync(0xffffffffu, dv, 2);
            dv += __shfl_xor_sync(0xffffffffu, dv, 1);
            if (lane == 0) G[pos] = dv;
        }
        __syncthreads();

        if (tid < 49) {
            int kx = tid % 7, ky = tid / 7;
            float xs = fminf(fmaxf(cx + (float)(kx - 3), 0.f), (float)(Wl - 1));
            float ys = fminf(fmaxf(cy + (float)(ky - 3), 0.f), (float)(Wl - 1));
            int x0 = min(max((int)floorf(xs), 0), Wl - 2);
            int y0 = min(max((int)floorf(ys), 0), Wl - 2);
            float wx = xs - (float)x0, wy = ys - (float)y0;
            int j = x0 - bx + 3;   // in [0,6], j+1 <= 7 (clamp cases verified)
            int i = y0 - by + 3;
            float g00 = G[i * 8 + j];
            float g01 = G[i * 8 + j + 1];
            float g10 = G[i * 8 + 8 + j];
            float g11 = G[i * 8 + 8 + j + 1];
            float val = g00 * (1.f - wx) * (1.f - wy) + g01 * wx * (1.f - wy)
                      + g10 * (1.f - wx) * wy + g11 * wx * wy;
            ob[p * 196 + l * 49 + tid] = val;
        }
        __syncthreads();
    }

    // Full-res feature bilinear sample (thread = channel)
    {
        float xs = fminf(fmaxf(u, 0.f), (float)(HH - 1));
        float ys = fminf(fmaxf(v, 0.f), (float)(HH - 1));
        int x0 = min(max((int)floorf(xs), 0), HH - 2);
        int y0 = min(max((int)floorf(ys), 0), HH - 2);
        float wx = xs - (float)x0, wy = ys - (float)y0;
        const float* b00 = base0 + ((size_t)(y0 * HH + x0) << 7);
        float v00 = b00[tid];
        float v01 = b00[CC + tid];
        float v10 = b00[(HH << 7) + tid];
        float v11 = b00[(HH << 7) + CC + tid];
        ob[588 + p * CC + tid] = v00 * (1.f - wx) * (1.f - wy) + v01 * wx * (1.f - wy)
                               + v10 * (1.f - wx) * wy + v11 * wx * wy;
    }
}

// ---------------------------------------------------------------------------
extern "C" void kernel_launch(void* const* d_in, const int* in_sizes, int n_in,
                              void* d_out, int out_size) {
    const float* fxy    = (const float*)d_in[0];
    const float* fyz    = (const float*)d_in[1];
    const float* fxz    = (const float*)d_in[2];
    const float* coords = (const float*)d_in[3];
    const int*   qt     = (const int*)d_in[4];
    float* out = (float*)d_out;

    // 1) transpose to channels-last
    {
        dim3 grid(HH * HH / 32, CC / 32, 3 * SS);
        dim3 block(32, 8);
        transpose_kernel<<<grid, block>>>(fxy, fyz, fxz);
    }
    // 2) pyramid pools
    {
        size_t t0 = (size_t)3 * SS * 64 * 64 * (CC / 4);
        pool_kernel<<<(int)((t0 + 255) / 256), 256>>>(0);
        size_t t1 = (size_t)3 * SS * 32 * 32 * (CC / 4);
        pool_kernel<<<(int)((t1 + 255) / 256), 256>>>(1);
        size_t t2 = (size_t)3 * SS * 16 * 16 * (CC / 4);
        pool_kernel<<<(int)((t2 + 255) / 256), 256>>>(2);
    }
    // 3) init track features
    {
        dim3 grid(NN, 3);
        init_kernel<<<grid, CC>>>(coords, qt);
    }
    // 4) main correlation + feature sampling
    {
        dim3 grid(NN, SS, 3);
        main_kernel<<<grid, 128>>>(coords, out);
    }
}

// round 3
// speedup vs baseline: 1.2387x; 1.2387x over previous
#include <cuda_runtime.h>
#include <cuda_fp16.h>
#include <cstdint>

#define SS 8
#define NN 512
#define CC 128
#define HH 128

// Scratch: channels-last fp16 fmap pyramid per plane + fp32 scaled init feats.
__device__ __half g_P0[(size_t)3 * SS * HH * HH * CC];     // [3*S][128][128][C]
__device__ __half g_P1[(size_t)3 * SS * 64 * 64 * CC];
__device__ __half g_P2[(size_t)3 * SS * 32 * 32 * CC];
__device__ __half g_P3[(size_t)3 * SS * 16 * 16 * CC];
__device__ float  g_T [(size_t)3 * NN * CC];               // t / sqrt(C), fp32

// ---------------------------------------------------------------------------
// Transpose [S,C,H,W] fp32 -> [S,H,W,C] fp16 per plane
// ---------------------------------------------------------------------------
__global__ void transpose_kernel(const float* __restrict__ fxy,
                                 const float* __restrict__ fyz,
                                 const float* __restrict__ fxz) {
    int ps = blockIdx.z;              // p*S + s
    int p = ps / SS, s = ps % SS;
    const float* src = (p == 0 ? fxy : (p == 1 ? fyz : fxz)) + (size_t)s * CC * HH * HH;
    __half* dst = g_P0 + (size_t)ps * HH * HH * CC;

    __shared__ float tile[32][33];
    int m0 = blockIdx.x * 32;         // pixel (h*W+w) tile
    int c0 = blockIdx.y * 32;         // channel tile
    int tx = threadIdx.x, ty = threadIdx.y;   // (32, 8)

#pragma unroll
    for (int k = 0; k < 4; k++) {
        int c = c0 + ty + k * 8;
        tile[ty + k * 8][tx] = src[(size_t)c * (HH * HH) + m0 + tx];
    }
    __syncthreads();
#pragma unroll
    for (int k = 0; k < 4; k++) {
        int m = m0 + ty + k * 8;
        dst[(size_t)m * CC + c0 + tx] = __float2half(tile[tx][ty + k * 8]);
    }
}

// ---------------------------------------------------------------------------
// 2x2 average pool, channels-last fp16 (fp32 internal math), 4 ch per thread
// ---------------------------------------------------------------------------
__device__ __forceinline__ float2 h2f(uint32_t u) {
    return __half22float2(*(const __half2*)&u);
}

__global__ void pool_kernel(int level) {
    const __half* src; __half* dst; int Ws;
    if (level == 0)      { src = g_P0; dst = g_P1; Ws = 128; }
    else if (level == 1) { src = g_P1; dst = g_P2; Ws = 64; }
    else                 { src = g_P2; dst = g_P3; Ws = 32; }
    int Wd = Ws >> 1;

    size_t idx = (size_t)blockIdx.x * blockDim.x + threadIdx.x;
    size_t total = (size_t)3 * SS * Wd * Wd * (CC / 4);
    if (idx >= total) return;

    int c4 = (int)(idx & 31);
    size_t r = idx >> 5;
    int xx = (int)(r % Wd); r /= Wd;
    int yy = (int)(r % Wd); r /= Wd;   // r = ps

    const __half* sp = src + (((r * Ws + 2 * yy) * Ws + 2 * xx) << 7) + (c4 << 2);
    uint2 A = *(const uint2*)sp;
    uint2 B = *(const uint2*)(sp + CC);
    uint2 Cq = *(const uint2*)(sp + ((size_t)Ws << 7));
    uint2 D = *(const uint2*)(sp + ((size_t)Ws << 7) + CC);

    float2 a0 = h2f(A.x), a1 = h2f(A.y);
    float2 b0 = h2f(B.x), b1 = h2f(B.y);
    float2 c0 = h2f(Cq.x), c1 = h2f(Cq.y);
    float2 d0 = h2f(D.x), d1 = h2f(D.y);

    __half2 o0 = __floats2half2_rn((a0.x + b0.x + c0.x + d0.x) * 0.25f,
                                   (a0.y + b0.y + c0.y + d0.y) * 0.25f);
    __half2 o1 = __floats2half2_rn((a1.x + b1.x + c1.x + d1.x) * 0.25f,
                                   (a1.y + b1.y + c1.y + d1.y) * 0.25f);
    uint2 o; o.x = *(uint32_t*)&o0; o.y = *(uint32_t*)&o1;
    *(uint2*)(dst + (((r * Wd + yy) * Wd + xx) << 7) + (c4 << 2)) = o;
}

// ---------------------------------------------------------------------------
// Init track features (fp32 accumulate from fp16 P0), pre-scaled 1/sqrt(C)
// ---------------------------------------------------------------------------
__global__ void init_kernel(const float* __restrict__ coords,
                            const int* __restrict__ qt) {
    int n = blockIdx.x, p = blockIdx.y, c = threadIdx.x;
    float x = coords[n * 3 + 0], y = coords[n * 3 + 1], z = coords[n * 3 + 2];
    float u = (p == 0) ? x : (p == 1 ? y : x);
    float v = (p == 0) ? y : z;
    int f = qt[n];
    const __half* base = g_P0 + (size_t)(p * SS + f) * HH * HH * CC;

    u = fminf(fmaxf(u, 0.f), (float)(HH - 1));
    v = fminf(fmaxf(v, 0.f), (float)(HH - 1));
    int x0 = min(max((int)floorf(u), 0), HH - 2);
    int y0 = min(max((int)floorf(v), 0), HH - 2);
    float wx = u - (float)x0, wy = v - (float)y0;

    const __half* b00 = base + ((size_t)(y0 * HH + x0) << 7);
    float v00 = __half2float(b00[c]);
    float v01 = __half2float(b00[CC + c]);
    float v10 = __half2float(b00[(HH << 7) + c]);
    float v11 = __half2float(b00[(HH << 7) + CC + c]);
    float val = v00 * (1.f - wx) * (1.f - wy) + v01 * wx * (1.f - wy)
              + v10 * (1.f - wx) * wy + v11 * wx * wy;
    g_T[(size_t)(p * NN + n) * CC + c] = val * 0.08838834764831845f; // 1/sqrt(128)
}

// ---------------------------------------------------------------------------
// Main: per (plane, s, n): 8x8 grid of corr dots per level -> 49 taps,
// plus full-res bilinear feature sample. fp16 loads, fp32 accumulation.
// ---------------------------------------------------------------------------
__global__ void __launch_bounds__(128) main_kernel(const float* __restrict__ coords,
                                                   float* __restrict__ out) {
    int n = blockIdx.x, s = blockIdx.y, p = blockIdx.z;
    int tid = threadIdx.x, lane = tid & 31, w = tid >> 5;
    int ps = p * SS + s;

    const float* cc = coords + (size_t)(s * NN + n) * 3;
    float x = cc[0], y = cc[1], z = cc[2];
    float u = (p == 0) ? x : (p == 1 ? y : x);
    float v = (p == 0) ? y : z;

    __shared__ float sT[CC];
    __shared__ float G[64];
    sT[tid] = g_T[(size_t)(p * NN + n) * CC + tid];
    __syncthreads();
    float4 tt = ((const float4*)sT)[lane];   // channels lane*4 .. lane*4+3

    float* ob = out + ((size_t)s * NN + n) * 972;

    const __half* base0 = g_P0 + (size_t)ps * HH * HH * CC;
    const __half* base1 = g_P1 + (size_t)ps * 64 * 64 * CC;
    const __half* base2 = g_P2 + (size_t)ps * 32 * 32 * CC;
    const __half* base3 = g_P3 + (size_t)ps * 16 * 16 * CC;

#pragma unroll
    for (int l = 0; l < 4; l++) {
        const int Wl = HH >> l;
        const float sc = 1.0f / (float)(1 << l);
        const __half* base = (l == 0) ? base0 : (l == 1) ? base1 : (l == 2) ? base2 : base3;

        float cx = u * sc, cy = v * sc;
        int bx = (int)floorf(cx), by = (int)floorf(cy);

        // 64 grid dot products; warp handles 16 positions (good MLP)
#pragma unroll
        for (int q = 0; q < 16; q++) {
            int pos = w * 16 + q;
            int gi = pos >> 3, gj = pos & 7;
            int gy = min(max(by - 3 + gi, 0), Wl - 1);
            int gx = min(max(bx - 3 + gj, 0), Wl - 1);
            uint2 raw = *(const uint2*)(base + ((size_t)(gy * Wl + gx) << 7) + (lane << 2));
            float2 f0 = h2f(raw.x), f1 = h2f(raw.y);
            float dv = f0.x * tt.x + f0.y * tt.y + f1.x * tt.z + f1.y * tt.w;
            dv += __shfl_xor_sync(0xffffffffu, dv, 16);
            dv += __shfl_xor_sync(0xffffffffu, dv, 8);
            dv += __shfl_xor_sync(0xffffffffu, dv, 4);
            dv += __shfl_xor_sync(0xffffffffu, dv, 2);
            dv += __shfl_xor_sync(0xffffffffu, dv, 1);
            if (lane == 0) G[pos] = dv;
        }
        __syncthreads();

        if (tid < 49) {
            int kx = tid % 7, ky = tid / 7;
            float xs = fminf(fmaxf(cx + (float)(kx - 3), 0.f), (float)(Wl - 1));
            float ys = fminf(fmaxf(cy + (float)(ky - 3), 0.f), (float)(Wl - 1));
            int x0 = min(max((int)floorf(xs), 0), Wl - 2);
            int y0 = min(max((int)floorf(ys), 0), Wl - 2);
            float wx = xs - (float)x0, wy = ys - (float)y0;
            int j = x0 - bx + 3;   // in [0,6], j+1 <= 7 (clamp cases verified)
            int i = y0 - by + 3;
            float g00 = G[i * 8 + j];
            float g01 = G[i * 8 + j + 1];
            float g10 = G[i * 8 + 8 + j];
            float g11 = G[i * 8 + 8 + j + 1];
            float val = g00 * (1.f - wx) * (1.f - wy) + g01 * wx * (1.f - wy)
                      + g10 * (1.f - wx) * wy + g11 * wx * wy;
            ob[p * 196 + l * 49 + tid] = val;
        }
        __syncthreads();
    }

    // Full-res feature bilinear sample (thread = channel)
    {
        float xs = fminf(fmaxf(u, 0.f), (float)(HH - 1));
        float ys = fminf(fmaxf(v, 0.f), (float)(HH - 1));
        int x0 = min(max((int)floorf(xs), 0), HH - 2);
        int y0 = min(max((int)floorf(ys), 0), HH - 2);
        float wx = xs - (float)x0, wy = ys - (float)y0;
        const __half* b00 = base0 + ((size_t)(y0 * HH + x0) << 7);
        float v00 = __half2float(b00[tid]);
        float v01 = __half2float(b00[CC + tid]);
        float v10 = __half2float(b00[(HH << 7) + tid]);
        float v11 = __half2float(b00[(HH << 7) + CC + tid]);
        ob[588 + p * CC + tid] = v00 * (1.f - wx) * (1.f - wy) + v01 * wx * (1.f - wy)
                               + v10 * (1.f - wx) * wy + v11 * wx * wy;
    }
}

// ---------------------------------------------------------------------------
extern "C" void kernel_launch(void* const* d_in, const int* in_sizes, int n_in,
                              void* d_out, int out_size) {
    const float* fxy    = (const float*)d_in[0];
    const float* fyz    = (const float*)d_in[1];
    const float* fxz    = (const float*)d_in[2];
    const float* coords = (const float*)d_in[3];
    const int*   qt     = (const int*)d_in[4];
    float* out = (float*)d_out;

    // 1) transpose + fp16 convert to channels-last
    {
        dim3 grid(HH * HH / 32, CC / 32, 3 * SS);
        dim3 block(32, 8);
        transpose_kernel<<<grid, block>>>(fxy, fyz, fxz);
    }
    // 2) pyramid pools
    {
        size_t t0 = (size_t)3 * SS * 64 * 64 * (CC / 4);
        pool_kernel<<<(int)((t0 + 255) / 256), 256>>>(0);
        size_t t1 = (size_t)3 * SS * 32 * 32 * (CC / 4);
        pool_kernel<<<(int)((t1 + 255) / 256), 256>>>(1);
        size_t t2 = (size_t)3 * SS * 16 * 16 * (CC / 4);
        pool_kernel<<<(int)((t2 + 255) / 256), 256>>>(2);
    }
    // 3) init track features
    {
        dim3 grid(NN, 3);
        init_kernel<<<grid, CC>>>(coords, qt);
    }
    // 4) main correlation + feature sampling
    {
        dim3 grid(NN, SS, 3);
        main_kernel<<<grid, 128>>>(coords, out);
    }
}

// round 4
// speedup vs baseline: 1.4916x; 1.2042x over previous
#include <cuda_runtime.h>
#include <cuda_fp16.h>
#include <cstdint>

#define SS 8
#define NN 512
#define CC 128
#define HH 128

// Scratch: channels-last fp16 fmap pyramid per plane + fp32 scaled init feats.
__device__ __half g_P0[(size_t)3 * SS * HH * HH * CC];     // [3*S][128][128][C]
__device__ __half g_P1[(size_t)3 * SS * 64 * 64 * CC];
__device__ __half g_P2[(size_t)3 * SS * 32 * 32 * CC];
__device__ __half g_P3[(size_t)3 * SS * 16 * 16 * CC];
__device__ float  g_T [(size_t)3 * NN * CC];               // t / sqrt(C), fp32

__device__ __forceinline__ float2 h2f(uint32_t u) {
    return __half22float2(*(const __half2*)&u);
}

// ---------------------------------------------------------------------------
// Transpose [S,C,H,W] fp32 -> [S,H,W,C] fp16 per plane
// ---------------------------------------------------------------------------
__global__ void transpose_kernel(const float* __restrict__ fxy,
                                 const float* __restrict__ fyz,
                                 const float* __restrict__ fxz) {
    int ps = blockIdx.z;              // p*S + s
    int p = ps / SS, s = ps % SS;
    const float* src = (p == 0 ? fxy : (p == 1 ? fyz : fxz)) + (size_t)s * CC * HH * HH;
    __half* dst = g_P0 + (size_t)ps * HH * HH * CC;

    __shared__ float tile[32][33];
    int m0 = blockIdx.x * 32;         // pixel (h*W+w) tile
    int c0 = blockIdx.y * 32;         // channel tile
    int tx = threadIdx.x, ty = threadIdx.y;   // (32, 8)

#pragma unroll
    for (int k = 0; k < 4; k++) {
        int c = c0 + ty + k * 8;
        tile[ty + k * 8][tx] = src[(size_t)c * (HH * HH) + m0 + tx];
    }
    __syncthreads();
#pragma unroll
    for (int k = 0; k < 4; k++) {
        int m = m0 + ty + k * 8;
        dst[(size_t)m * CC + c0 + tx] = __float2half(tile[tx][ty + k * 8]);
    }
}

// ---------------------------------------------------------------------------
// 2x2 average pool, channels-last fp16 (fp32 internal math), 4 ch per thread
// ---------------------------------------------------------------------------
__global__ void pool_kernel(int level) {
    const __half* src; __half* dst; int Ws;
    if (level == 0)      { src = g_P0; dst = g_P1; Ws = 128; }
    else if (level == 1) { src = g_P1; dst = g_P2; Ws = 64; }
    else                 { src = g_P2; dst = g_P3; Ws = 32; }
    int Wd = Ws >> 1;

    size_t idx = (size_t)blockIdx.x * blockDim.x + threadIdx.x;
    size_t total = (size_t)3 * SS * Wd * Wd * (CC / 4);
    if (idx >= total) return;

    int c4 = (int)(idx & 31);
    size_t r = idx >> 5;
    int xx = (int)(r % Wd); r /= Wd;
    int yy = (int)(r % Wd); r /= Wd;   // r = ps

    const __half* sp = src + (((r * Ws + 2 * yy) * Ws + 2 * xx) << 7) + (c4 << 2);
    uint2 A = *(const uint2*)sp;
    uint2 B = *(const uint2*)(sp + CC);
    uint2 Cq = *(const uint2*)(sp + ((size_t)Ws << 7));
    uint2 D = *(const uint2*)(sp + ((size_t)Ws << 7) + CC);

    float2 a0 = h2f(A.x), a1 = h2f(A.y);
    float2 b0 = h2f(B.x), b1 = h2f(B.y);
    float2 c0 = h2f(Cq.x), c1 = h2f(Cq.y);
    float2 d0 = h2f(D.x), d1 = h2f(D.y);

    __half2 o0 = __floats2half2_rn((a0.x + b0.x + c0.x + d0.x) * 0.25f,
                                   (a0.y + b0.y + c0.y + d0.y) * 0.25f);
    __half2 o1 = __floats2half2_rn((a1.x + b1.x + c1.x + d1.x) * 0.25f,
                                   (a1.y + b1.y + c1.y + d1.y) * 0.25f);
    uint2 o; o.x = *(uint32_t*)&o0; o.y = *(uint32_t*)&o1;
    *(uint2*)(dst + (((r * Wd + yy) * Wd + xx) << 7) + (c4 << 2)) = o;
}

// ---------------------------------------------------------------------------
// Init track features (fp32 accumulate from fp16 P0), pre-scaled 1/sqrt(C)
// ---------------------------------------------------------------------------
__global__ void init_kernel(const float* __restrict__ coords,
                            const int* __restrict__ qt) {
    int n = blockIdx.x, p = blockIdx.y, c = threadIdx.x;
    float x = coords[n * 3 + 0], y = coords[n * 3 + 1], z = coords[n * 3 + 2];
    float u = (p == 0) ? x : (p == 1 ? y : x);
    float v = (p == 0) ? y : z;
    int f = qt[n];
    const __half* base = g_P0 + (size_t)(p * SS + f) * HH * HH * CC;

    u = fminf(fmaxf(u, 0.f), (float)(HH - 1));
    v = fminf(fmaxf(v, 0.f), (float)(HH - 1));
    int x0 = min(max((int)floorf(u), 0), HH - 2);
    int y0 = min(max((int)floorf(v), 0), HH - 2);
    float wx = u - (float)x0, wy = v - (float)y0;

    const __half* b00 = base + ((size_t)(y0 * HH + x0) << 7);
    float v00 = __half2float(b00[c]);
    float v01 = __half2float(b00[CC + c]);
    float v10 = __half2float(b00[(HH << 7) + c]);
    float v11 = __half2float(b00[(HH << 7) + CC + c]);
    float val = v00 * (1.f - wx) * (1.f - wy) + v01 * wx * (1.f - wy)
              + v10 * (1.f - wx) * wy + v11 * wx * wy;
    g_T[(size_t)(p * NN + n) * CC + c] = val * 0.08838834764831845f; // 1/sqrt(128)
}

// ---------------------------------------------------------------------------
// Main: block = (n, s, p). Warp w computes level w's 8x8 grid of corr dots
// (16 lanes per position, uint4 loads, 4-level shfl reduce). Then all 128
// threads do 196 taps + 128-channel feature sample.
// ---------------------------------------------------------------------------
__global__ void __launch_bounds__(128) main_kernel(const float* __restrict__ coords,
                                                   float* __restrict__ out) {
    int n = blockIdx.x, s = blockIdx.y, p = blockIdx.z;
    int tid = threadIdx.x, lane = tid & 31, w = tid >> 5;
    int ps = p * SS + s;

    const float* cc = coords + (size_t)(s * NN + n) * 3;
    float x = cc[0], y = cc[1], z = cc[2];
    float u = (p == 0) ? x : (p == 1 ? y : x);
    float v = (p == 0) ? y : z;

    __shared__ float sT[CC];
    __shared__ float G[4][64];
    sT[tid] = g_T[(size_t)(p * NN + n) * CC + tid];
    __syncthreads();

    int li = lane & 15;                       // lane within 16-lane group
    // channels li*8 .. li*8+7
    float4 tA = ((const float4*)sT)[li * 2];
    float4 tB = ((const float4*)sT)[li * 2 + 1];

    const __half* base0 = g_P0 + (size_t)ps * HH * HH * CC;
    const __half* base1 = g_P1 + (size_t)ps * 64 * 64 * CC;
    const __half* base2 = g_P2 + (size_t)ps * 32 * 32 * CC;
    const __half* base3 = g_P3 + (size_t)ps * 16 * 16 * CC;

    // ---- grid phase: warp w handles level w ----
    {
        const int l = w;
        const int Wl = HH >> l;
        const float sc = 1.0f / (float)(1 << l);
        const __half* base = (l == 0) ? base0 : (l == 1) ? base1 : (l == 2) ? base2 : base3;

        float cx = u * sc, cy = v * sc;
        int bx = (int)floorf(cx), by = (int)floorf(cy);
        int hp = lane >> 4;                   // which of 2 positions this iter

#pragma unroll
        for (int it = 0; it < 32; it++) {
            int pos = it * 2 + hp;            // 0..63
            int gi = pos >> 3, gj = pos & 7;
            int gy = min(max(by - 3 + gi, 0), Wl - 1);
            int gx = min(max(bx - 3 + gj, 0), Wl - 1);
            uint4 raw = *(const uint4*)(base + ((size_t)(gy * Wl + gx) << 7) + (li << 3));
            float2 f0 = h2f(raw.x), f1 = h2f(raw.y), f2 = h2f(raw.z), f3 = h2f(raw.w);
            float dv = f0.x * tA.x + f0.y * tA.y + f1.x * tA.z + f1.y * tA.w
                     + f2.x * tB.x + f2.y * tB.y + f3.x * tB.z + f3.y * tB.w;
            dv += __shfl_xor_sync(0xffffffffu, dv, 8);
            dv += __shfl_xor_sync(0xffffffffu, dv, 4);
            dv += __shfl_xor_sync(0xffffffffu, dv, 2);
            dv += __shfl_xor_sync(0xffffffffu, dv, 1);
            if (li == 0) G[l][pos] = dv;
        }
    }
    __syncthreads();

    float* ob = out + ((size_t)s * NN + n) * 972;

    // ---- tap phase: 196 taps over 128 threads ----
#pragma unroll
    for (int t = tid; t < 196; t += 128) {
        int l = t / 49, k = t % 49;
        int Wl = HH >> l;
        float sc = (l == 0) ? 1.f : (l == 1) ? 0.5f : (l == 2) ? 0.25f : 0.125f;
        float cx = u * sc, cy = v * sc;
        int bx = (int)floorf(cx), by = (int)floorf(cy);
        int kx = k % 7, ky = k / 7;
        float xs = fminf(fmaxf(cx + (float)(kx - 3), 0.f), (float)(Wl - 1));
        float ys = fminf(fmaxf(cy + (float)(ky - 3), 0.f), (float)(Wl - 1));
        int x0 = min(max((int)floorf(xs), 0), Wl - 2);
        int y0 = min(max((int)floorf(ys), 0), Wl - 2);
        float wx = xs - (float)x0, wy = ys - (float)y0;
        int j = x0 - bx + 3;   // in [0,6], j+1 <= 7 (clamp cases verified)
        int i = y0 - by + 3;
        float g00 = G[l][i * 8 + j];
        float g01 = G[l][i * 8 + j + 1];
        float g10 = G[l][i * 8 + 8 + j];
        float g11 = G[l][i * 8 + 8 + j + 1];
        ob[p * 196 + t] = g00 * (1.f - wx) * (1.f - wy) + g01 * wx * (1.f - wy)
                        + g10 * (1.f - wx) * wy + g11 * wx * wy;
    }

    // ---- full-res feature bilinear sample (thread = channel) ----
    {
        float xs = fminf(fmaxf(u, 0.f), (float)(HH - 1));
        float ys = fminf(fmaxf(v, 0.f), (float)(HH - 1));
        int x0 = min(max((int)floorf(xs), 0), HH - 2);
        int y0 = min(max((int)floorf(ys), 0), HH - 2);
        float wx = xs - (float)x0, wy = ys - (float)y0;
        const __half* b00 = base0 + ((size_t)(y0 * HH + x0) << 7);
        float v00 = __half2float(b00[tid]);
        float v01 = __half2float(b00[CC + tid]);
        float v10 = __half2float(b00[(HH << 7) + tid]);
        float v11 = __half2float(b00[(HH << 7) + CC + tid]);
        ob[588 + p * CC + tid] = v00 * (1.f - wx) * (1.f - wy) + v01 * wx * (1.f - wy)
                               + v10 * (1.f - wx) * wy + v11 * wx * wy;
    }
}

// ---------------------------------------------------------------------------
extern "C" void kernel_launch(void* const* d_in, const int* in_sizes, int n_in,
                              void* d_out, int out_size) {
    const float* fxy    = (const float*)d_in[0];
    const float* fyz    = (const float*)d_in[1];
    const float* fxz    = (const float*)d_in[2];
    const float* coords = (const float*)d_in[3];
    const int*   qt     = (const int*)d_in[4];
    float* out = (float*)d_out;

    // 1) transpose + fp16 convert to channels-last
    {
        dim3 grid(HH * HH / 32, CC / 32, 3 * SS);
        dim3 block(32, 8);
        transpose_kernel<<<grid, block>>>(fxy, fyz, fxz);
    }
    // 2) pyramid pools
    {
        size_t t0 = (size_t)3 * SS * 64 * 64 * (CC / 4);
        pool_kernel<<<(int)((t0 + 255) / 256), 256>>>(0);
        size_t t1 = (size_t)3 * SS * 32 * 32 * (CC / 4);
        pool_kernel<<<(int)((t1 + 255) / 256), 256>>>(1);
        size_t t2 = (size_t)3 * SS * 16 * 16 * (CC / 4);
        pool_kernel<<<(int)((t2 + 255) / 256), 256>>>(2);
    }
    // 3) init track features
    {
        dim3 grid(NN, 3);
        init_kernel<<<grid, CC>>>(coords, qt);
    }
    // 4) main correlation + feature sampling
    {
        dim3 grid(NN, SS, 3);
        main_kernel<<<grid, 128>>>(coords, out);
    }
}